// round 1
// baseline (speedup 1.0000x reference)
#include <cuda_runtime.h>
#include <math.h>

// Problem dims (fixed)
constexpr int B_ = 2;
constexpr int T_ = 4096;
constexpr int C_ = 2048;
constexpr int H_ = 32;
constexpr int K_ = 64;
constexpr int CA_ = H_ * K_;      // 2048
constexpr int M_ = B_ * T_;       // 8192 rows

// ---------------------------------------------------------------------------
// Scratch (device globals; no allocation allowed)
// ---------------------------------------------------------------------------
__device__ float g_xr[(size_t)M_ * C_];
__device__ float g_xk[(size_t)M_ * C_];
__device__ float g_xv[(size_t)M_ * C_];
__device__ float g_xg[(size_t)M_ * C_];
__device__ float g_r [(size_t)M_ * CA_];
__device__ float g_k [(size_t)M_ * CA_];
__device__ float g_v [(size_t)M_ * CA_];
__device__ float g_g [(size_t)M_ * CA_];
__device__ float g_y [(size_t)M_ * CA_];
__device__ float g_z [(size_t)M_ * CA_];

// ---------------------------------------------------------------------------
// Kernel 1: time-mix (lerp) for r/k/v/g + shift_state_out
// ---------------------------------------------------------------------------
__global__ __launch_bounds__(256) void mix_kernel(
    const float* __restrict__ x, const float* __restrict__ shift,
    const float* __restrict__ mk, const float* __restrict__ mv,
    const float* __restrict__ mr, const float* __restrict__ mg,
    float* __restrict__ shift_out)
{
    size_t i4 = (size_t)blockIdx.x * 256 + threadIdx.x;   // float4 index
    size_t idx = i4 * 4;
    int c = (int)(idx % C_);
    size_t bt = idx / C_;
    int t = (int)(bt % T_);
    int b = (int)(bt / T_);

    float4 xc = *(const float4*)(x + idx);
    float4 xx;
    if (t == 0) xx = *(const float4*)(shift + (size_t)b * C_ + c);
    else        xx = *(const float4*)(x + idx - C_);

    float dx = xc.x - xx.x, dy = xc.y - xx.y, dz = xc.z - xx.z, dw = xc.w - xx.w;

    float4 m;
    float4 o;
    m = *(const float4*)(mr + c);
    o.x = fmaf(m.x, dx, xx.x); o.y = fmaf(m.y, dy, xx.y);
    o.z = fmaf(m.z, dz, xx.z); o.w = fmaf(m.w, dw, xx.w);
    *(float4*)(g_xr + idx) = o;
    m = *(const float4*)(mk + c);
    o.x = fmaf(m.x, dx, xx.x); o.y = fmaf(m.y, dy, xx.y);
    o.z = fmaf(m.z, dz, xx.z); o.w = fmaf(m.w, dw, xx.w);
    *(float4*)(g_xk + idx) = o;
    m = *(const float4*)(mv + c);
    o.x = fmaf(m.x, dx, xx.x); o.y = fmaf(m.y, dy, xx.y);
    o.z = fmaf(m.z, dz, xx.z); o.w = fmaf(m.w, dw, xx.w);
    *(float4*)(g_xv + idx) = o;
    m = *(const float4*)(mg + c);
    o.x = fmaf(m.x, dx, xx.x); o.y = fmaf(m.y, dy, xx.y);
    o.z = fmaf(m.z, dz, xx.z); o.w = fmaf(m.w, dw, xx.w);
    *(float4*)(g_xg + idx) = o;

    if (t == T_ - 1) *(float4*)(shift_out + (size_t)b * C_ + c) = xc;
}

// ---------------------------------------------------------------------------
// Kernel 2: SGEMM  C[M,N] = A[M,K] * B[N,K]^T   (both row-major, K contiguous)
// 128x128 block tile, BK=16, 256 threads, 8x8 per thread
// ---------------------------------------------------------------------------
constexpr int BM = 128, BN = 128, BK = 16;

__global__ __launch_bounds__(256) void sgemm_nt(
    const float* __restrict__ A, const float* __restrict__ B,
    float* __restrict__ C, int M, int N, int K)
{
    __shared__ float As[BK][BM + 4];
    __shared__ float Bs[BK][BN + 4];

    const int tid  = threadIdx.x;
    const int brow = blockIdx.y * BM;
    const int bcol = blockIdx.x * BN;
    const int tx = tid % 16;          // col group
    const int ty = tid / 16;          // row group
    const int lrow = tid / 4;         // 0..63
    const int lcol = (tid % 4) * 4;   // 0,4,8,12

    float acc[8][8];
#pragma unroll
    for (int i = 0; i < 8; i++)
#pragma unroll
        for (int j = 0; j < 8; j++) acc[i][j] = 0.f;

    const float* Ap0 = A + (size_t)(brow + lrow) * K + lcol;
    const float* Ap1 = A + (size_t)(brow + lrow + 64) * K + lcol;
    const float* Bp0 = B + (size_t)(bcol + lrow) * K + lcol;
    const float* Bp1 = B + (size_t)(bcol + lrow + 64) * K + lcol;

    for (int k0 = 0; k0 < K; k0 += BK) {
        float4 a0 = *(const float4*)(Ap0 + k0);
        float4 a1 = *(const float4*)(Ap1 + k0);
        float4 b0 = *(const float4*)(Bp0 + k0);
        float4 b1 = *(const float4*)(Bp1 + k0);

        __syncthreads();
        As[lcol + 0][lrow] = a0.x; As[lcol + 1][lrow] = a0.y;
        As[lcol + 2][lrow] = a0.z; As[lcol + 3][lrow] = a0.w;
        As[lcol + 0][lrow + 64] = a1.x; As[lcol + 1][lrow + 64] = a1.y;
        As[lcol + 2][lrow + 64] = a1.z; As[lcol + 3][lrow + 64] = a1.w;
        Bs[lcol + 0][lrow] = b0.x; Bs[lcol + 1][lrow] = b0.y;
        Bs[lcol + 2][lrow] = b0.z; Bs[lcol + 3][lrow] = b0.w;
        Bs[lcol + 0][lrow + 64] = b1.x; Bs[lcol + 1][lrow + 64] = b1.y;
        Bs[lcol + 2][lrow + 64] = b1.z; Bs[lcol + 3][lrow + 64] = b1.w;
        __syncthreads();

#pragma unroll
        for (int kk = 0; kk < BK; kk++) {
            float ar[8], br[8];
            *(float4*)(ar)     = *(const float4*)&As[kk][ty * 8];
            *(float4*)(ar + 4) = *(const float4*)&As[kk][ty * 8 + 4];
            *(float4*)(br)     = *(const float4*)&Bs[kk][tx * 8];
            *(float4*)(br + 4) = *(const float4*)&Bs[kk][tx * 8 + 4];
#pragma unroll
            for (int i = 0; i < 8; i++)
#pragma unroll
                for (int j = 0; j < 8; j++)
                    acc[i][j] = fmaf(ar[i], br[j], acc[i][j]);
        }
    }

#pragma unroll
    for (int i = 0; i < 8; i++) {
        size_t ro = (size_t)(brow + ty * 8 + i) * N + bcol + tx * 8;
        float4 c0 = make_float4(acc[i][0], acc[i][1], acc[i][2], acc[i][3]);
        float4 c1 = make_float4(acc[i][4], acc[i][5], acc[i][6], acc[i][7]);
        *(float4*)(C + ro)     = c0;
        *(float4*)(C + ro + 4) = c1;
    }
}

// ---------------------------------------------------------------------------
// Kernel 3: WKV sequential scan.
// Grid: B*H*2 blocks (v split in halves of 32). 128 threads/block.
// Each thread owns S[k0..k0+16][v] in registers.
// ---------------------------------------------------------------------------
__global__ __launch_bounds__(128) void wkv_scan_kernel(
    const float* __restrict__ r, const float* __restrict__ kk,
    const float* __restrict__ vv, const float* __restrict__ state_in,
    const float* __restrict__ decay, const float* __restrict__ faaaa,
    float* __restrict__ y, float* __restrict__ state_out)
{
    __shared__ float sr[64][64];
    __shared__ float sk[64][64];
    __shared__ float sv[64][32];

    const int tid  = threadIdx.x;
    const int warp = tid >> 5, lane = tid & 31;
    const int vl = warp * 8 + (lane >> 2);   // 0..31 local v
    const int kg = lane & 3;
    const int bid = blockIdx.x;
    const int vh = bid & 1;
    const int h  = (bid >> 1) & (H_ - 1);
    const int b  = bid >> 6;
    const int vg = vh * 32 + vl;             // global v 0..63
    const int k0 = kg * 16;

    float s[16], w[16], u[16];
#pragma unroll
    for (int i = 0; i < 16; i++) {
        int kidx = k0 + i;
        s[i] = state_in[(((size_t)b * H_ + h) * K_ + kidx) * K_ + vg];
        w[i] = expf(-expf(decay[h * K_ + kidx]));
        u[i] = faaaa[h * K_ + kidx];
    }

    const size_t rbase = (((size_t)b * T_) * H_ + h) * K_;   // (b,0,h,0)
    const int step = H_ * K_;                                 // 2048

    for (int c0 = 0; c0 < T_; c0 += 64) {
#pragma unroll
        for (int i = 0; i < 8; i++) {
            int idx = i * 128 + tid;           // 0..1023
            int st = idx >> 4, off = (idx & 15) << 2;
            size_t gi = rbase + (size_t)(c0 + st) * step + off;
            *(float4*)&sr[st][off] = *(const float4*)(r + gi);
            *(float4*)&sk[st][off] = *(const float4*)(kk + gi);
        }
#pragma unroll
        for (int i = 0; i < 4; i++) {
            int idx = i * 128 + tid;           // 0..511
            int st = idx >> 3, off = (idx & 7) << 2;
            size_t gi = rbase + (size_t)(c0 + st) * step + vh * 32 + off;
            *(float4*)&sv[st][off] = *(const float4*)(vv + gi);
        }
        __syncthreads();

        for (int t = 0; t < 64; t++) {
            float rt[16], kt[16];
#pragma unroll
            for (int q = 0; q < 4; q++) {
                *(float4*)&rt[q * 4] = *(const float4*)&sr[t][k0 + q * 4];
                *(float4*)&kt[q * 4] = *(const float4*)&sk[t][k0 + q * 4];
            }
            float vt = sv[t][vl];
            float acc0 = 0.f, acc1 = 0.f;
#pragma unroll
            for (int i = 0; i < 8; i++) {
                float a = kt[i] * vt;
                float tmp = fmaf(u[i], a, s[i]);
                acc0 = fmaf(rt[i], tmp, acc0);
                s[i] = fmaf(w[i], s[i], a);
            }
#pragma unroll
            for (int i = 8; i < 16; i++) {
                float a = kt[i] * vt;
                float tmp = fmaf(u[i], a, s[i]);
                acc1 = fmaf(rt[i], tmp, acc1);
                s[i] = fmaf(w[i], s[i], a);
            }
            float acc = acc0 + acc1;
            acc += __shfl_xor_sync(0xffffffffu, acc, 1);
            acc += __shfl_xor_sync(0xffffffffu, acc, 2);
            if (kg == 0)
                y[rbase + (size_t)(c0 + t) * step + vg] = acc;
        }
        __syncthreads();
    }

#pragma unroll
    for (int i = 0; i < 16; i++)
        state_out[(((size_t)b * H_ + h) * K_ + (k0 + i)) * K_ + vg] = s[i];
}

// ---------------------------------------------------------------------------
// Kernel 4: per-head groupnorm (two-pass in regs) + SiLU(g) gating
// One warp per (b,t,h) group of 64; 2 elems/lane.
// ---------------------------------------------------------------------------
__global__ __launch_bounds__(256) void gn_gate_kernel(
    const float* __restrict__ gamma, const float* __restrict__ beta)
{
    int warp = threadIdx.x >> 5, lane = threadIdx.x & 31;
    size_t gid = (size_t)blockIdx.x * 8 + warp;     // (b*T+t)*H + h
    int h = (int)(gid % H_);
    size_t base = gid * 64 + lane * 2;

    float2 yv = *(const float2*)(g_y + base);
    float a = yv.x * 0.125f, c = yv.y * 0.125f;

    float sum = a + c;
#pragma unroll
    for (int o = 16; o; o >>= 1) sum += __shfl_xor_sync(0xffffffffu, sum, o);
    float mu = sum * (1.f / 64.f);

    float d0 = a - mu, d1 = c - mu;
    float sq = d0 * d0 + d1 * d1;
#pragma unroll
    for (int o = 16; o; o >>= 1) sq += __shfl_xor_sync(0xffffffffu, sq, o);
    float rs = rsqrtf(sq * (1.f / 64.f) + 1e-5f);

    int cc = h * 64 + lane * 2;
    float z0 = fmaf(d0 * rs, gamma[cc],     beta[cc]);
    float z1 = fmaf(d1 * rs, gamma[cc + 1], beta[cc + 1]);

    float2 gv = *(const float2*)(g_g + base);
    z0 *= gv.x / (1.f + expf(-gv.x));
    z1 *= gv.y / (1.f + expf(-gv.y));
    *(float2*)(g_z + base) = make_float2(z0, z1);
}

// ---------------------------------------------------------------------------
// Host launch
// ---------------------------------------------------------------------------
extern "C" void kernel_launch(void* const* d_in, const int* in_sizes, int n_in,
                              void* d_out, int out_size)
{
    const float* x        = (const float*)d_in[0];
    const float* shift_in = (const float*)d_in[1];
    const float* wkv_in   = (const float*)d_in[2];
    const float* tm_k     = (const float*)d_in[3];
    const float* tm_v     = (const float*)d_in[4];
    const float* tm_r     = (const float*)d_in[5];
    const float* tm_g     = (const float*)d_in[6];
    const float* decay    = (const float*)d_in[7];
    const float* faaaa    = (const float*)d_in[8];
    const float* W_r      = (const float*)d_in[9];
    const float* W_k      = (const float*)d_in[10];
    const float* W_v      = (const float*)d_in[11];
    const float* W_g      = (const float*)d_in[12];
    const float* W_o      = (const float*)d_in[13];
    const float* ln_gamma = (const float*)d_in[14];
    const float* ln_beta  = (const float*)d_in[15];

    float* out       = (float*)d_out;
    float* shift_out = out + (size_t)M_ * C_;
    float* state_out = shift_out + (size_t)B_ * C_;

    float *xr, *xk, *xv, *xg, *rr, *kk, *vv, *gg, *yy, *zz;
    cudaGetSymbolAddress((void**)&xr, g_xr);
    cudaGetSymbolAddress((void**)&xk, g_xk);
    cudaGetSymbolAddress((void**)&xv, g_xv);
    cudaGetSymbolAddress((void**)&xg, g_xg);
    cudaGetSymbolAddress((void**)&rr, g_r);
    cudaGetSymbolAddress((void**)&kk, g_k);
    cudaGetSymbolAddress((void**)&vv, g_v);
    cudaGetSymbolAddress((void**)&gg, g_g);
    cudaGetSymbolAddress((void**)&yy, g_y);
    cudaGetSymbolAddress((void**)&zz, g_z);

    // 1) time-mix
    mix_kernel<<<(size_t)M_ * C_ / 4 / 256, 256>>>(x, shift_in, tm_k, tm_v, tm_r, tm_g, shift_out);

    // 2) projections
    dim3 gemm_grid(CA_ / BN, M_ / BM);
    sgemm_nt<<<gemm_grid, 256>>>(xr, W_r, rr, M_, CA_, C_);
    sgemm_nt<<<gemm_grid, 256>>>(xk, W_k, kk, M_, CA_, C_);
    sgemm_nt<<<gemm_grid, 256>>>(xv, W_v, vv, M_, CA_, C_);
    sgemm_nt<<<gemm_grid, 256>>>(xg, W_g, gg, M_, CA_, C_);

    // 3) WKV scan
    wkv_scan_kernel<<<B_ * H_ * 2, 128>>>(rr, kk, vv, wkv_in, decay, faaaa, yy, state_out);

    // 4) groupnorm + gate
    gn_gate_kernel<<<(size_t)M_ * H_ / 8, 256>>>(ln_gamma, ln_beta);

    // 5) output projection
    dim3 gemm_grid_o(C_ / BN, M_ / BM);
    sgemm_nt<<<gemm_grid_o, 256>>>(zz, W_o, out, M_, C_, C_);
}

// round 11
// speedup vs baseline: 1.6401x; 1.6401x over previous
#include <cuda_runtime.h>
#include <cuda_bf16.h>
#include <math.h>
#include <stdint.h>

// Problem dims (fixed)
constexpr int B_ = 2;
constexpr int T_ = 4096;
constexpr int C_ = 2048;
constexpr int H_ = 32;
constexpr int K_ = 64;
constexpr int CA_ = H_ * K_;      // 2048
constexpr int M_ = B_ * T_;       // 8192

// ---------------------------------------------------------------------------
// Scratch (device globals; no allocation allowed)
// ---------------------------------------------------------------------------
__device__ __nv_bfloat16 g_ah[(size_t)4 * M_ * C_];   // xr,xk,xv,xg hi
__device__ __nv_bfloat16 g_al[(size_t)4 * M_ * C_];   // lo
__device__ __nv_bfloat16 g_wh[(size_t)5 * C_ * CA_];  // W_r,W_k,W_v,W_g,W_o hi
__device__ __nv_bfloat16 g_wl[(size_t)5 * C_ * CA_];
__device__ float g_r[(size_t)M_ * CA_];
__device__ float g_k[(size_t)M_ * CA_];
__device__ float g_v[(size_t)M_ * CA_];
__device__ float g_g[(size_t)M_ * CA_];
__device__ float g_y[(size_t)M_ * CA_];
__device__ __nv_bfloat16 g_zh[(size_t)M_ * CA_];
__device__ __nv_bfloat16 g_zl[(size_t)M_ * CA_];

// ---------------------------------------------------------------------------
// PTX helpers (portable: cp.async sm80+, ldmatrix sm75+, mma.bf16 sm80+)
// ---------------------------------------------------------------------------
__device__ __forceinline__ uint32_t smem_u32(const void* p) {
    uint32_t a;
    asm("{ .reg .u64 t; cvta.to.shared.u64 t, %1; cvt.u32.u64 %0, t; }" : "=r"(a) : "l"(p));
    return a;
}
__device__ __forceinline__ void cpa16(uint32_t d, const void* s) {
    asm volatile("cp.async.cg.shared.global [%0], [%1], 16;" :: "r"(d), "l"(s));
}
#define CP_COMMIT()  asm volatile("cp.async.commit_group;" ::: "memory")
#define CP_WAIT(N)   asm volatile("cp.async.wait_group %0;" :: "n"(N) : "memory")

__device__ __forceinline__ void ldsm4(uint32_t* r, uint32_t addr) {
    asm volatile("ldmatrix.sync.aligned.m8n8.x4.shared.b16 {%0,%1,%2,%3}, [%4];"
                 : "=r"(r[0]), "=r"(r[1]), "=r"(r[2]), "=r"(r[3]) : "r"(addr));
}
__device__ __forceinline__ void mma16816(float* c, const uint32_t* a,
                                         uint32_t b0, uint32_t b1) {
    asm volatile(
        "mma.sync.aligned.m16n8k16.row.col.f32.bf16.bf16.f32 "
        "{%0,%1,%2,%3}, {%4,%5,%6,%7}, {%8,%9}, {%0,%1,%2,%3};"
        : "+f"(c[0]), "+f"(c[1]), "+f"(c[2]), "+f"(c[3])
        : "r"(a[0]), "r"(a[1]), "r"(a[2]), "r"(a[3]), "r"(b0), "r"(b1));
}

// ---------------------------------------------------------------------------
// split helpers
// ---------------------------------------------------------------------------
__device__ __forceinline__ void store_split4(__nv_bfloat16* hi, __nv_bfloat16* lo,
                                             size_t idx, float4 o) {
    __nv_bfloat162 h01, h23, l01, l23;
    h01.x = __float2bfloat16(o.x); h01.y = __float2bfloat16(o.y);
    h23.x = __float2bfloat16(o.z); h23.y = __float2bfloat16(o.w);
    l01.x = __float2bfloat16(o.x - __bfloat162float(h01.x));
    l01.y = __float2bfloat16(o.y - __bfloat162float(h01.y));
    l23.x = __float2bfloat16(o.z - __bfloat162float(h23.x));
    l23.y = __float2bfloat16(o.w - __bfloat162float(h23.y));
    *(__nv_bfloat162*)(hi + idx)     = h01;
    *(__nv_bfloat162*)(hi + idx + 2) = h23;
    *(__nv_bfloat162*)(lo + idx)     = l01;
    *(__nv_bfloat162*)(lo + idx + 2) = l23;
}

// ---------------------------------------------------------------------------
// Kernel 1: time-mix + split to bf16 hi/lo
// ---------------------------------------------------------------------------
__global__ __launch_bounds__(256) void mix_kernel(
    const float* __restrict__ x, const float* __restrict__ shift,
    const float* __restrict__ mk, const float* __restrict__ mv,
    const float* __restrict__ mr, const float* __restrict__ mg,
    float* __restrict__ shift_out)
{
    size_t idx = ((size_t)blockIdx.x * 256 + threadIdx.x) * 4;
    int c = (int)(idx % C_);
    size_t bt = idx / C_;
    int t = (int)(bt % T_);
    int b = (int)(bt / T_);

    float4 xc = *(const float4*)(x + idx);
    float4 xx;
    if (t == 0) xx = *(const float4*)(shift + (size_t)b * C_ + c);
    else        xx = *(const float4*)(x + idx - C_);

    float dx = xc.x - xx.x, dy = xc.y - xx.y, dz = xc.z - xx.z, dw = xc.w - xx.w;
    const size_t seg = (size_t)M_ * C_;

    float4 m, o;
    m = *(const float4*)(mr + c);
    o.x = fmaf(m.x, dx, xx.x); o.y = fmaf(m.y, dy, xx.y);
    o.z = fmaf(m.z, dz, xx.z); o.w = fmaf(m.w, dw, xx.w);
    store_split4(g_ah, g_al, idx, o);
    m = *(const float4*)(mk + c);
    o.x = fmaf(m.x, dx, xx.x); o.y = fmaf(m.y, dy, xx.y);
    o.z = fmaf(m.z, dz, xx.z); o.w = fmaf(m.w, dw, xx.w);
    store_split4(g_ah + seg, g_al + seg, idx, o);
    m = *(const float4*)(mv + c);
    o.x = fmaf(m.x, dx, xx.x); o.y = fmaf(m.y, dy, xx.y);
    o.z = fmaf(m.z, dz, xx.z); o.w = fmaf(m.w, dw, xx.w);
    store_split4(g_ah + 2 * seg, g_al + 2 * seg, idx, o);
    m = *(const float4*)(mg + c);
    o.x = fmaf(m.x, dx, xx.x); o.y = fmaf(m.y, dy, xx.y);
    o.z = fmaf(m.z, dz, xx.z); o.w = fmaf(m.w, dw, xx.w);
    store_split4(g_ah + 3 * seg, g_al + 3 * seg, idx, o);

    if (t == T_ - 1) *(float4*)(shift_out + (size_t)b * C_ + c) = xc;
}

// ---------------------------------------------------------------------------
// Kernel 2: weight split fp32 -> bf16 hi/lo
// ---------------------------------------------------------------------------
__global__ __launch_bounds__(256) void wsplit_kernel(
    const float* __restrict__ w, __nv_bfloat16* __restrict__ hi,
    __nv_bfloat16* __restrict__ lo)
{
    size_t idx = ((size_t)blockIdx.x * 256 + threadIdx.x) * 4;
    float4 v = *(const float4*)(w + idx);
    store_split4(hi, lo, idx, v);
}

// ---------------------------------------------------------------------------
// Kernel 3: mma.sync bf16x3 GEMM  C[M,N] = A[M,K] * B[N,K]^T
// 128x128 CTA tile, BK=32, 256 threads (8 warps, warp tile 64x32),
// 4-stage cp.async pipeline. Padded-row smem (80B stride) for ldmatrix.
// ---------------------------------------------------------------------------
constexpr int GM = 128, GN = 128, BK2 = 32;
constexpr int STAGES = 4;
constexpr uint32_t RS = 80;            // bytes per smem row (32 bf16 + pad)
constexpr uint32_t MATB = 128 * RS;    // 10240 B per matrix per stage
constexpr uint32_t STGB = 4 * MATB;    // Ah,Al,Bh,Bl = 40960 B
constexpr uint32_t GEMM_SMEM = STAGES * STGB;  // 163840 B

__device__ __forceinline__ void load_stage(
    uint32_t st, int k0, int tid, int brow, int bcol, int K,
    const __nv_bfloat16* __restrict__ Ah, const __nv_bfloat16* __restrict__ Al,
    const __nv_bfloat16* __restrict__ Bh, const __nv_bfloat16* __restrict__ Bl)
{
    const int r = tid >> 1;                 // 0..127
    const int half = tid & 1;               // 0/1 -> 32B halves of the 64B row
    const uint32_t drow = st + (uint32_t)r * RS + (uint32_t)half * 32;
    const size_t ga = (size_t)(brow + r) * K + (size_t)k0 * BK2 + half * 16;
    const size_t gb = (size_t)(bcol + r) * K + (size_t)k0 * BK2 + half * 16;
    cpa16(drow,                Ah + ga);
    cpa16(drow + 16,           Ah + ga + 8);
    cpa16(drow + MATB,         Al + ga);
    cpa16(drow + MATB + 16,    Al + ga + 8);
    cpa16(drow + 2 * MATB,     Bh + gb);
    cpa16(drow + 2 * MATB + 16, Bh + gb + 8);
    cpa16(drow + 3 * MATB,     Bl + gb);
    cpa16(drow + 3 * MATB + 16, Bl + gb + 8);
}

__global__ __launch_bounds__(256, 1) void gemm_bf16x3(
    const __nv_bfloat16* __restrict__ Ah, const __nv_bfloat16* __restrict__ Al,
    const __nv_bfloat16* __restrict__ Bh, const __nv_bfloat16* __restrict__ Bl,
    float* __restrict__ Cc, int M, int N, int K)
{
    extern __shared__ char smraw[];
    const uint32_t sb = smem_u32(smraw);
    const int tid = threadIdx.x, wid = tid >> 5, lane = tid & 31;
    const int wm = wid & 1, wn = wid >> 1;          // warp grid 2(m) x 4(n)
    const int brow = blockIdx.y * GM, bcol = blockIdx.x * GN;

    const uint32_t lrow = lane & 15;                // ldmatrix row within 16
    const uint32_t lkh = (uint32_t)(lane >> 4);     // k-half selector (16B)

    float acc[4][4][4];
#pragma unroll
    for (int i = 0; i < 4; i++)
#pragma unroll
        for (int j = 0; j < 4; j++)
#pragma unroll
            for (int q = 0; q < 4; q++) acc[i][j][q] = 0.f;

    const int NK = K / BK2;

    // Pipeline fill: stages 0..STAGES-2
#pragma unroll
    for (int s = 0; s < STAGES - 1; s++) {
        load_stage(sb + (uint32_t)s * STGB, s, tid, brow, bcol, K, Ah, Al, Bh, Bl);
        CP_COMMIT();
    }

    for (int k0 = 0; k0 < NK; k0++) {
        if (k0 < NK - 2)      { CP_WAIT(2); }
        else if (k0 == NK - 2){ CP_WAIT(1); }
        else                  { CP_WAIT(0); }
        __syncthreads();   // all warps done with the stage we are about to overwrite

        if (k0 + STAGES - 1 < NK) {
            load_stage(sb + (uint32_t)((k0 + STAGES - 1) % STAGES) * STGB,
                       k0 + STAGES - 1, tid, brow, bcol, K, Ah, Al, Bh, Bl);
            CP_COMMIT();
        }

        const uint32_t sa = sb + (uint32_t)(k0 % STAGES) * STGB;
        const uint32_t aBase = sa + (uint32_t)(wm * 64 + lrow) * RS + lkh * 16;
        const uint32_t bBase = sa + 2 * MATB + (uint32_t)(wn * 32 + lrow) * RS + lkh * 16;

#pragma unroll
        for (int kh = 0; kh < 2; kh++) {
            const uint32_t ko = (uint32_t)kh * 32;   // 16 bf16 = 32B
            uint32_t ah[4][4], al[4][4], bh[2][4], bl[2][4];
#pragma unroll
            for (int i = 0; i < 4; i++) {
                uint32_t ad = aBase + (uint32_t)(i * 16) * RS + ko;
                ldsm4(ah[i], ad);
                ldsm4(al[i], ad + MATB);
            }
#pragma unroll
            for (int j = 0; j < 2; j++) {
                uint32_t bd = bBase + (uint32_t)(j * 16) * RS + ko;
                ldsm4(bh[j], bd);
                ldsm4(bl[j], bd + MATB);
            }
#pragma unroll
            for (int i = 0; i < 4; i++) {
#pragma unroll
                for (int jj = 0; jj < 4; jj++) {
                    const int p = jj >> 1, o = jj & 1;
                    float* cc = acc[i][jj];
                    mma16816(cc, ah[i], bh[p][o], bh[p][o + 2]);
                    mma16816(cc, ah[i], bl[p][o], bl[p][o + 2]);
                    mma16816(cc, al[i], bh[p][o], bh[p][o + 2]);
                }
            }
        }
    }

    // Epilogue: registers -> global
    const int mrow0 = brow + wm * 64 + (lane >> 2);
    const int ncol0 = bcol + wn * 32 + (lane & 3) * 2;
#pragma unroll
    for (int i = 0; i < 4; i++) {
#pragma unroll
        for (int jj = 0; jj < 4; jj++) {
            const int m = mrow0 + i * 16;
            const int n = ncol0 + jj * 8;
            float2 v0 = make_float2(acc[i][jj][0], acc[i][jj][1]);
            float2 v1 = make_float2(acc[i][jj][2], acc[i][jj][3]);
            *(float2*)(Cc + (size_t)m * N + n)       = v0;
            *(float2*)(Cc + (size_t)(m + 8) * N + n) = v1;
        }
    }
}

// ---------------------------------------------------------------------------
// Kernel 4: WKV sequential scan
// ---------------------------------------------------------------------------
__global__ __launch_bounds__(128) void wkv_scan_kernel(
    const float* __restrict__ r, const float* __restrict__ kk,
    const float* __restrict__ vv, const float* __restrict__ state_in,
    const float* __restrict__ decay, const float* __restrict__ faaaa,
    float* __restrict__ y, float* __restrict__ state_out)
{
    __shared__ float sr[64][64];
    __shared__ float sk[64][64];
    __shared__ float sv[64][32];

    const int tid  = threadIdx.x;
    const int warp = tid >> 5, lane = tid & 31;
    const int vl = warp * 8 + (lane >> 2);
    const int kg = lane & 3;
    const int bid = blockIdx.x;
    const int vh = bid & 1;
    const int h  = (bid >> 1) & (H_ - 1);
    const int b  = bid >> 6;
    const int vg = vh * 32 + vl;
    const int k0 = kg * 16;

    float s[16], w[16], u[16];
#pragma unroll
    for (int i = 0; i < 16; i++) {
        int kidx = k0 + i;
        s[i] = state_in[(((size_t)b * H_ + h) * K_ + kidx) * K_ + vg];
        w[i] = expf(-expf(decay[h * K_ + kidx]));
        u[i] = faaaa[h * K_ + kidx];
    }

    const size_t rbase = (((size_t)b * T_) * H_ + h) * K_;
    const int step = H_ * K_;

    for (int c0 = 0; c0 < T_; c0 += 64) {
#pragma unroll
        for (int i = 0; i < 8; i++) {
            int idx = i * 128 + tid;
            int st = idx >> 4, off = (idx & 15) << 2;
            size_t gi = rbase + (size_t)(c0 + st) * step + off;
            *(float4*)&sr[st][off] = *(const float4*)(r + gi);
            *(float4*)&sk[st][off] = *(const float4*)(kk + gi);
        }
#pragma unroll
        for (int i = 0; i < 4; i++) {
            int idx = i * 128 + tid;
            int st = idx >> 3, off = (idx & 7) << 2;
            size_t gi = rbase + (size_t)(c0 + st) * step + vh * 32 + off;
            *(float4*)&sv[st][off] = *(const float4*)(vv + gi);
        }
        __syncthreads();

        for (int t = 0; t < 64; t++) {
            float rt[16], kt[16];
#pragma unroll
            for (int q = 0; q < 4; q++) {
                *(float4*)&rt[q * 4] = *(const float4*)&sr[t][k0 + q * 4];
                *(float4*)&kt[q * 4] = *(const float4*)&sk[t][k0 + q * 4];
            }
            float vt = sv[t][vl];
            float acc0 = 0.f, acc1 = 0.f;
#pragma unroll
            for (int i = 0; i < 8; i++) {
                float a = kt[i] * vt;
                float tmp = fmaf(u[i], a, s[i]);
                acc0 = fmaf(rt[i], tmp, acc0);
                s[i] = fmaf(w[i], s[i], a);
            }
#pragma unroll
            for (int i = 8; i < 16; i++) {
                float a = kt[i] * vt;
                float tmp = fmaf(u[i], a, s[i]);
                acc1 = fmaf(rt[i], tmp, acc1);
                s[i] = fmaf(w[i], s[i], a);
            }
            float acc = acc0 + acc1;
            acc += __shfl_xor_sync(0xffffffffu, acc, 1);
            acc += __shfl_xor_sync(0xffffffffu, acc, 2);
            if (kg == 0)
                y[rbase + (size_t)(c0 + t) * step + vg] = acc;
        }
        __syncthreads();
    }

#pragma unroll
    for (int i = 0; i < 16; i++)
        state_out[(((size_t)b * H_ + h) * K_ + (k0 + i)) * K_ + vg] = s[i];
}

// ---------------------------------------------------------------------------
// Kernel 5: groupnorm + SiLU gate, split to bf16 hi/lo
// ---------------------------------------------------------------------------
__global__ __launch_bounds__(256) void gn_gate_kernel(
    const float* __restrict__ gamma, const float* __restrict__ beta)
{
    int warp = threadIdx.x >> 5, lane = threadIdx.x & 31;
    size_t gid = (size_t)blockIdx.x * 8 + warp;
    int h = (int)(gid % H_);
    size_t base = gid * 64 + lane * 2;

    float2 yv = *(const float2*)(g_y + base);
    float a = yv.x * 0.125f, c = yv.y * 0.125f;

    float sum = a + c;
#pragma unroll
    for (int o = 16; o; o >>= 1) sum += __shfl_xor_sync(0xffffffffu, sum, o);
    float mu = sum * (1.f / 64.f);

    float d0 = a - mu, d1 = c - mu;
    float sq = d0 * d0 + d1 * d1;
#pragma unroll
    for (int o = 16; o; o >>= 1) sq += __shfl_xor_sync(0xffffffffu, sq, o);
    float rs = rsqrtf(sq * (1.f / 64.f) + 1e-5f);

    int cc = h * 64 + lane * 2;
    float z0 = fmaf(d0 * rs, gamma[cc],     beta[cc]);
    float z1 = fmaf(d1 * rs, gamma[cc + 1], beta[cc + 1]);

    float2 gv = *(const float2*)(g_g + base);
    z0 *= gv.x / (1.f + expf(-gv.x));
    z1 *= gv.y / (1.f + expf(-gv.y));

    __nv_bfloat162 hh, ll;
    hh.x = __float2bfloat16(z0); hh.y = __float2bfloat16(z1);
    ll.x = __float2bfloat16(z0 - __bfloat162float(hh.x));
    ll.y = __float2bfloat16(z1 - __bfloat162float(hh.y));
    *(__nv_bfloat162*)(g_zh + base) = hh;
    *(__nv_bfloat162*)(g_zl + base) = ll;
}

// ---------------------------------------------------------------------------
// Host launch
// ---------------------------------------------------------------------------
extern "C" void kernel_launch(void* const* d_in, const int* in_sizes, int n_in,
                              void* d_out, int out_size)
{
    const float* x        = (const float*)d_in[0];
    const float* shift_in = (const float*)d_in[1];
    const float* wkv_in   = (const float*)d_in[2];
    const float* tm_k     = (const float*)d_in[3];
    const float* tm_v     = (const float*)d_in[4];
    const float* tm_r     = (const float*)d_in[5];
    const float* tm_g     = (const float*)d_in[6];
    const float* decay    = (const float*)d_in[7];
    const float* faaaa    = (const float*)d_in[8];
    const float* W_r      = (const float*)d_in[9];
    const float* W_k      = (const float*)d_in[10];
    const float* W_v      = (const float*)d_in[11];
    const float* W_g      = (const float*)d_in[12];
    const float* W_o      = (const float*)d_in[13];
    const float* ln_gamma = (const float*)d_in[14];
    const float* ln_beta  = (const float*)d_in[15];

    float* out       = (float*)d_out;
    float* shift_out = out + (size_t)M_ * C_;
    float* state_out = shift_out + (size_t)B_ * C_;

    __nv_bfloat16 *ah, *al, *wh, *wl, *zh, *zl;
    float *rr, *kk, *vv, *gg, *yy;
    cudaGetSymbolAddress((void**)&ah, g_ah);
    cudaGetSymbolAddress((void**)&al, g_al);
    cudaGetSymbolAddress((void**)&wh, g_wh);
    cudaGetSymbolAddress((void**)&wl, g_wl);
    cudaGetSymbolAddress((void**)&zh, g_zh);
    cudaGetSymbolAddress((void**)&zl, g_zl);
    cudaGetSymbolAddress((void**)&rr, g_r);
    cudaGetSymbolAddress((void**)&kk, g_k);
    cudaGetSymbolAddress((void**)&vv, g_v);
    cudaGetSymbolAddress((void**)&gg, g_g);
    cudaGetSymbolAddress((void**)&yy, g_y);

    cudaFuncSetAttribute(gemm_bf16x3, cudaFuncAttributeMaxDynamicSharedMemorySize,
                         GEMM_SMEM);

    const size_t aseg = (size_t)M_ * C_;
    const size_t wseg = (size_t)C_ * CA_;

    // 1) time-mix + split
    mix_kernel<<<(int)(aseg / 4 / 256), 256>>>(x, shift_in, tm_k, tm_v, tm_r, tm_g,
                                               shift_out);
    // 2) weight splits
    wsplit_kernel<<<(int)(wseg / 4 / 256), 256>>>(W_r, wh,            wl);
    wsplit_kernel<<<(int)(wseg / 4 / 256), 256>>>(W_k, wh + wseg,     wl + wseg);
    wsplit_kernel<<<(int)(wseg / 4 / 256), 256>>>(W_v, wh + 2 * wseg, wl + 2 * wseg);
    wsplit_kernel<<<(int)(wseg / 4 / 256), 256>>>(W_g, wh + 3 * wseg, wl + 3 * wseg);
    wsplit_kernel<<<(int)(wseg / 4 / 256), 256>>>(W_o, wh + 4 * wseg, wl + 4 * wseg);

    // 3) projections (mma.sync bf16x3)
    dim3 gg_grid(CA_ / GN, M_ / GM);
    gemm_bf16x3<<<gg_grid, 256, GEMM_SMEM>>>(ah,            al,            wh,            wl,            rr, M_, CA_, C_);
    gemm_bf16x3<<<gg_grid, 256, GEMM_SMEM>>>(ah + aseg,     al + aseg,     wh + wseg,     wl + wseg,     kk, M_, CA_, C_);
    gemm_bf16x3<<<gg_grid, 256, GEMM_SMEM>>>(ah + 2 * aseg, al + 2 * aseg, wh + 2 * wseg, wl + 2 * wseg, vv, M_, CA_, C_);
    gemm_bf16x3<<<gg_grid, 256, GEMM_SMEM>>>(ah + 3 * aseg, al + 3 * aseg, wh + 3 * wseg, wl + 3 * wseg, gg, M_, CA_, C_);

    // 4) WKV scan
    wkv_scan_kernel<<<B_ * H_ * 2, 128>>>(rr, kk, vv, wkv_in, decay, faaaa, yy,
                                          state_out);

    // 5) groupnorm + gate + split
    gn_gate_kernel<<<(int)((size_t)M_ * H_ / 8), 256>>>(ln_gamma, ln_beta);

    // 6) output projection
    dim3 go_grid(C_ / GN, M_ / GM);
    gemm_bf16x3<<<go_grid, 256, GEMM_SMEM>>>(zh, zl, wh + 4 * wseg, wl + 4 * wseg,
                                             out, M_, C_, CA_);
}